// round 4
// baseline (speedup 1.0000x reference)
#include <cuda_runtime.h>
#include <cstdint>

// MaxUnpooling2D gather, one thread per TWO adjacent 2x2 windows (w, w+1) per c4.
//   B=16, H=W=128, C=64, UP=2 -> HO=WO=256.
//   mask always lands inside its own 2x2 window:
//   out[b,ho,wo,c] = (mask[b,ho/2,wo/2,c] == (ho*WO+wo)*C + c) ? upd[...] : 0
//
// Per thread: 4 x LDG.128 (mask+upd for 2 pixels, front-batched -> MLP=4),
//             8 x STG.128 (2 output rows x 4 output pixels, contiguous per warp).
// Total threads: 16*128*64*16 = 2,097,152.

__global__ void __launch_bounds__(256)
unpool_window2_kernel(const float4* __restrict__ upd,
                      const int4*  __restrict__ mask,
                      float4* __restrict__ out) {
    int g = blockIdx.x * blockDim.x + threadIdx.x;   // 0 .. 2^21-1

    int c4 = g & 15;            // float4 slot within the 64 channels
    int wp = (g >> 4) & 63;     // w-pair index: covers w0=2*wp, w1=2*wp+1
    int h  = (g >> 10) & 127;
    int b  = g >> 17;

    int w0 = wp << 1;

    // input vec4 indices
    int in0 = ((((b << 7) + h) << 7) + w0) * 16 + c4;
    int in1 = in0 + 16;

    // Front-batch all 4 loads (MLP=4). Streaming: zero reuse chip-wide.
    int4   m0 = __ldcs(&mask[in0]);
    int4   m1 = __ldcs(&mask[in1]);
    float4 u0 = __ldcs(&upd[in0]);
    float4 u1 = __ldcs(&upd[in1]);

    int ho  = h << 1;
    int wo0 = w0 << 1;          // left col of first window (= wp*4)

    // flat output ELEMENT index of first channel at (ho, wo0):
    int t00 = (((ho << 8) + wo0) << 6) + (c4 << 2);
    // pixel deltas: +64 per wo step, +16384 per ho step
    // output VEC4 index of (b, ho, wo0, c4):
    int o00 = ((((b << 8) + ho) << 8) + wo0) * 16 + c4;
    // vec4 deltas: +16 per wo step, +4096 per ho step

    float4 r;

    // ---- row ho: wo0, wo0+1 (window 0), wo0+2, wo0+3 (window 1) ----
    r.x = (m0.x == t00    ) ? u0.x : 0.0f;
    r.y = (m0.y == t00 + 1) ? u0.y : 0.0f;
    r.z = (m0.z == t00 + 2) ? u0.z : 0.0f;
    r.w = (m0.w == t00 + 3) ? u0.w : 0.0f;
    __stcs(&out[o00], r);

    r.x = (m0.x == t00 + 64) ? u0.x : 0.0f;
    r.y = (m0.y == t00 + 65) ? u0.y : 0.0f;
    r.z = (m0.z == t00 + 66) ? u0.z : 0.0f;
    r.w = (m0.w == t00 + 67) ? u0.w : 0.0f;
    __stcs(&out[o00 + 16], r);

    r.x = (m1.x == t00 + 128) ? u1.x : 0.0f;
    r.y = (m1.y == t00 + 129) ? u1.y : 0.0f;
    r.z = (m1.z == t00 + 130) ? u1.z : 0.0f;
    r.w = (m1.w == t00 + 131) ? u1.w : 0.0f;
    __stcs(&out[o00 + 32], r);

    r.x = (m1.x == t00 + 192) ? u1.x : 0.0f;
    r.y = (m1.y == t00 + 193) ? u1.y : 0.0f;
    r.z = (m1.z == t00 + 194) ? u1.z : 0.0f;
    r.w = (m1.w == t00 + 195) ? u1.w : 0.0f;
    __stcs(&out[o00 + 48], r);

    // ---- row ho+1 ----
    int t10 = t00 + 16384;      // +WO*C
    int o10 = o00 + 4096;       // +WO*C/4

    r.x = (m0.x == t10    ) ? u0.x : 0.0f;
    r.y = (m0.y == t10 + 1) ? u0.y : 0.0f;
    r.z = (m0.z == t10 + 2) ? u0.z : 0.0f;
    r.w = (m0.w == t10 + 3) ? u0.w : 0.0f;
    __stcs(&out[o10], r);

    r.x = (m0.x == t10 + 64) ? u0.x : 0.0f;
    r.y = (m0.y == t10 + 65) ? u0.y : 0.0f;
    r.z = (m0.z == t10 + 66) ? u0.z : 0.0f;
    r.w = (m0.w == t10 + 67) ? u0.w : 0.0f;
    __stcs(&out[o10 + 16], r);

    r.x = (m1.x == t10 + 128) ? u1.x : 0.0f;
    r.y = (m1.y == t10 + 129) ? u1.y : 0.0f;
    r.z = (m1.z == t10 + 130) ? u1.z : 0.0f;
    r.w = (m1.w == t10 + 131) ? u1.w : 0.0f;
    __stcs(&out[o10 + 32], r);

    r.x = (m1.x == t10 + 192) ? u1.x : 0.0f;
    r.y = (m1.y == t10 + 193) ? u1.y : 0.0f;
    r.z = (m1.z == t10 + 194) ? u1.z : 0.0f;
    r.w = (m1.w == t10 + 195) ? u1.w : 0.0f;
    __stcs(&out[o10 + 48], r);
}

extern "C" void kernel_launch(void* const* d_in, const int* in_sizes, int n_in,
                              void* d_out, int out_size) {
    const float4* upd  = (const float4*)d_in[0];   // updates: [16,128,128,64] f32
    const int4*   mask = (const int4*)  d_in[1];   // mask:    [16,128,128,64] i32
    float4*       out  = (float4*)d_out;           // out:     [16,256,256,64] f32

    const int total_threads = 16 * 128 * 64 * 16;  // 2,097,152
    const int threads = 256;
    const int blocks = total_threads / threads;    // 8192

    unpool_window2_kernel<<<blocks, threads>>>(upd, mask, out);
}

// round 5
// speedup vs baseline: 1.0040x; 1.0040x over previous
#include <cuda_runtime.h>
#include <cstdint>

// MaxUnpooling2D gather with 256-bit (v8) global ld/st (sm_100+).
//   B=16, H=W=128, C=64, UP=2 -> HO=WO=256.
//   mask always lands inside its own 2x2 window:
//   out[b,ho,wo,c] = (mask[b,ho/2,wo/2,c] == (ho*WO+wo)*C + c) ? upd[...] : 0
//
// Thread = (b, h, w, c8), c8 in 0..7 (8-float chunk of the 64 channels).
// Per thread: 2 x LDG.256 (mask, upd), 4 x STG.256 (the 2x2 window slots).
// Total threads: 16*128*128*8 = 2,097,152.

__device__ __forceinline__ void ldg_v8_f32(const float* p, float u[8]) {
    asm volatile("ld.global.v8.f32 {%0,%1,%2,%3,%4,%5,%6,%7}, [%8];"
                 : "=f"(u[0]), "=f"(u[1]), "=f"(u[2]), "=f"(u[3]),
                   "=f"(u[4]), "=f"(u[5]), "=f"(u[6]), "=f"(u[7])
                 : "l"(p));
}

__device__ __forceinline__ void ldg_v8_b32(const int* p, int m[8]) {
    asm volatile("ld.global.v8.b32 {%0,%1,%2,%3,%4,%5,%6,%7}, [%8];"
                 : "=r"(m[0]), "=r"(m[1]), "=r"(m[2]), "=r"(m[3]),
                   "=r"(m[4]), "=r"(m[5]), "=r"(m[6]), "=r"(m[7])
                 : "l"(p));
}

__device__ __forceinline__ void stg_v8_f32(float* p, const float s[8]) {
    asm volatile("st.global.v8.f32 [%0], {%1,%2,%3,%4,%5,%6,%7,%8};"
                 :: "l"(p),
                    "f"(s[0]), "f"(s[1]), "f"(s[2]), "f"(s[3]),
                    "f"(s[4]), "f"(s[5]), "f"(s[6]), "f"(s[7])
                 : "memory");
}

__device__ __forceinline__ void emit_pos(float* p, int tbase,
                                         const int m[8], const float u[8]) {
    float s[8];
#pragma unroll
    for (int i = 0; i < 8; i++)
        s[i] = (m[i] == tbase + i) ? u[i] : 0.0f;
    stg_v8_f32(p, s);
}

__global__ void __launch_bounds__(256)
unpool_v8_kernel(const float* __restrict__ upd,
                 const int*  __restrict__ mask,
                 float* __restrict__ out) {
    int g = blockIdx.x * blockDim.x + threadIdx.x;   // 0 .. 2^21-1

    int c8 = g & 7;             // which 8-float chunk of the 64 channels
    int w  = (g >> 3) & 127;
    int h  = (g >> 10) & 127;
    int b  = g >> 17;

    // input 8-elem chunk index: ((b*128 + h)*128 + w)*8 + c8
    int in_chunk = ((((b << 7) + h) << 7) + w) * 8 + c8;

    int   m[8];
    float u[8];
    ldg_v8_b32(mask + in_chunk * 8, m);
    ldg_v8_f32(upd  + in_chunk * 8, u);

    int ho = h << 1;
    int wo = w << 1;

    // flat output ELEMENT index of this chunk's first channel at (ho, wo):
    int t00 = (((ho << 8) + wo) << 6) + (c8 << 3);
    int t10 = t00 + 16384;      // +WO*C for ho+1

    // output 8-elem chunk index of (b, ho, wo, c8):
    int o00 = ((((b << 8) + ho) << 8) + wo) * 8 + c8;
    // deltas (in chunks): +8 per wo step, +2048 per ho step

    emit_pos(out + (o00        ) * 8, t00,       m, u);   // (ho,   wo  )
    emit_pos(out + (o00 +    8 ) * 8, t00 + 64,  m, u);   // (ho,   wo+1)
    emit_pos(out + (o00 + 2048 ) * 8, t10,       m, u);   // (ho+1, wo  )
    emit_pos(out + (o00 + 2056 ) * 8, t10 + 64,  m, u);   // (ho+1, wo+1)
}

extern "C" void kernel_launch(void* const* d_in, const int* in_sizes, int n_in,
                              void* d_out, int out_size) {
    const float* upd  = (const float*)d_in[0];   // updates: [16,128,128,64] f32
    const int*   mask = (const int*)  d_in[1];   // mask:    [16,128,128,64] i32
    float*       out  = (float*)d_out;           // out:     [16,256,256,64] f32

    const int total_threads = 16 * 128 * 128 * 8; // 2,097,152
    const int threads = 256;
    const int blocks = total_threads / threads;   // 8192

    unpool_v8_kernel<<<blocks, threads>>>(upd, mask, out);
}